// round 17
// baseline (speedup 1.0000x reference)
#include <cuda_runtime.h>
#include <cuda_fp16.h>
#include <cuda_bf16.h>
#include <cstdint>

// CustomStellarEncoder: Linear+BN+ReLU -> SAGEConv(mean) -> BN
// R17: GEMM instruction-count cut: (a) paired {kq,kq+4} hi/lo operand layout
//      -> LDS.128 (halves LDS issues), (b) bf16x2 split via packed cvt +
//      bit-ops (fill ~40% fewer instr). Same math as R16 (412.2us).

#define D_IN 256
#define HID 128
#define EPS 1e-5f
#define N_MAX 100000
#define E_MAX 3200000

// ================= scratch =================
__device__ float g_y1[(size_t)N_MAX * HID];
__device__ float g_msg[(size_t)N_MAX * HID];
__device__ float g_y2[(size_t)N_MAX * HID];
__device__ __half2 g_feat16[(size_t)N_MAX * 64];   // fp16 mirror of feat
__device__ int   g_cnt[N_MAX];
__device__ int   g_fill[N_MAX];
__device__ int   g_rowstart[N_MAX + 1];
__device__ int   g_srcsorted[E_MAX];
__device__ int   g_bsum[128];
__device__ float g_sum[2][HID];
__device__ float g_sumsq[2][HID];
__device__ float g_scale[2][HID];
__device__ float g_shift[2][HID];
// weight images, paired layout: [chunk 0..3][kqp 0..15][n 0..129] x 8 u16
//   u16[8] = {hi_e,hi_o,lo_e,lo_o (kq), hi_e,hi_o,lo_e,lo_o (kq+4)}
__device__ uint16_t g_w1d[4 * 16 * 130 * 8];
__device__ uint16_t g_w2d[4 * 16 * 130 * 8];

// ================= bf16 split helpers =================
// split two floats -> (hi bf16x2, lo bf16x2)
__device__ __forceinline__ uint2 split2(float f0, float f1) {
    __nv_bfloat162 h = __floats2bfloat162_rn(f0, f1);   // .x=f0 lo16, .y=f1 hi16
    uint32_t hu = *(uint32_t*)&h;
    float hf0 = __uint_as_float(hu << 16);
    float hf1 = __uint_as_float(hu & 0xffff0000u);
    __nv_bfloat162 l = __floats2bfloat162_rn(f0 - hf0, f1 - hf1);
    return make_uint2(hu, *(uint32_t*)&l);
}

__device__ __forceinline__ void mma_bf16(float* d, uint32_t a0, uint32_t a1,
                                         uint32_t a2, uint32_t a3,
                                         uint32_t b0, uint32_t b1) {
    asm volatile(
        "mma.sync.aligned.m16n8k16.row.col.f32.bf16.bf16.f32 "
        "{%0,%1,%2,%3}, {%4,%5,%6,%7}, {%8,%9}, {%0,%1,%2,%3};"
        : "+f"(d[0]), "+f"(d[1]), "+f"(d[2]), "+f"(d[3])
        : "r"(a0), "r"(a1), "r"(a2), "r"(a3), "r"(b0), "r"(b1));
}

// ================= weight image prep (paired bf16 hi/lo) =================
// wset 0: W1 [256x128]; wset 1: rows 0-127 = Wl, rows 128-255 = Wr
__global__ void wprep_kernel(const float* __restrict__ W1,
                             const float* __restrict__ Wl,
                             const float* __restrict__ Wr) {
    int idx = blockIdx.x * blockDim.x + threadIdx.x;
    if (idx >= 2 * 256 * 128) return;
    int wset = idx >> 15;
    int rem  = idx & 32767;
    int k = rem >> 7;
    int nn = rem & 127;
    float v;
    if (wset == 0) v = W1[k * 128 + nn];
    else           v = (k < 128) ? Wl[k * 128 + nn] : Wr[(k - 128) * 128 + nn];
    __nv_bfloat16 h = __float2bfloat16(v);
    __nv_bfloat16 l = __float2bfloat16(v - __bfloat162float(h));
    int chunk = k >> 6;
    int kk = k & 63;
    int kqc = kk >> 1;            // 0..31
    int p = k & 1;
    int t = kqc >> 3;
    int s = (kqc >> 2) & 1;       // pair member: kq (0) or kq+4 (1)
    int l4 = kqc & 3;
    int kqp = t * 4 + l4;
    uint32_t base = (uint32_t)(((chunk * 16 + kqp) * 130 + nn) << 3);
    uint16_t* dst = wset ? g_w2d : g_w1d;
    dst[base + s * 4 + p]     = *(uint16_t*)&h;
    dst[base + s * 4 + 2 + p] = *(uint16_t*)&l;
}

// ================= bf16 GEMM + fused BN stats =================
// mode 0: A row = x[row, 0:256] (stride 256), W = g_w1d, out = g_y1, stats 0
// mode 1: A row = [g_msg fp32 | g_feat16 fp16], W = g_w2d, out = g_y2, stats 1
// smem: A [128 rows][20 uint4] = 40960 B ; B [16 kqp][130 uint4] = 33280 B
#define A_ST4 20
#define B_ST4 130
#define SM_B_OFF3 40960
#define SM_GTOTAL (SM_B_OFF3 + 16 * 130 * 16)   // 74240

__global__ __launch_bounds__(256, 2) void tc_gemm_kernel(
        int mode, const float* __restrict__ xptr,
        const float* __restrict__ bias, int n) {
    extern __shared__ char smem[];
    uint4* As4 = (uint4*)smem;                  // [128][20]
    uint4* Bs4 = (uint4*)(smem + SM_B_OFF3);    // [16][130]

    int tid = threadIdx.x;
    int lane = tid & 31;
    int wid = tid >> 5;
    int row0 = blockIdx.x * 128;
    int wrow = wid * 16;

    float d[16][4];
#pragma unroll
    for (int t = 0; t < 16; t++)
#pragma unroll
        for (int q = 0; q < 4; q++) d[t][q] = 0.f;

    const uint16_t* wimg = mode ? g_w2d : g_w1d;

    for (int c = 0; c < 4; c++) {
        int k0 = c * 64;
        // ---- fill A chunk: 128 rows x 64 k, paired {kq,kq+4} hi/lo uint4 ----
        {
            int r = tid >> 1;
            int cb = (tid & 1) * 32;      // k offset within chunk
            int grow = row0 + r;
            bool valid = grow < n;
            float f[32];
            if (valid) {
                if (mode == 1 && k0 >= 128) {
                    const uint2* src = (const uint2*)(g_feat16 +
                        (size_t)grow * 64 + ((k0 - 128 + cb) >> 1));
#pragma unroll
                    for (int j = 0; j < 8; j++) {
                        uint2 raw = src[j];
                        float2 f0 = __half22float2(*(__half2*)&raw.x);
                        float2 f1 = __half22float2(*(__half2*)&raw.y);
                        f[j * 4 + 0] = f0.x; f[j * 4 + 1] = f0.y;
                        f[j * 4 + 2] = f1.x; f[j * 4 + 3] = f1.y;
                    }
                } else {
                    const float* src = (mode == 0)
                        ? xptr + (size_t)grow * 256 + k0 + cb
                        : g_msg + (size_t)grow * 128 + k0 + cb;
#pragma unroll
                    for (int j = 0; j < 8; j++) {
                        float4 v = *(const float4*)(src + j * 4);
                        f[j * 4 + 0] = v.x; f[j * 4 + 1] = v.y;
                        f[j * 4 + 2] = v.z; f[j * 4 + 3] = v.w;
                    }
                }
            } else {
#pragma unroll
                for (int q = 0; q < 32; q++) f[q] = 0.f;
            }
#pragma unroll
            for (int p = 0; p < 8; p++) {
                int lq1 = (p & 3) + ((p >> 2) << 3);   // local kq of pair head
                int lq2 = lq1 + 4;
                uint2 a = split2(f[2 * lq1], f[2 * lq1 + 1]);
                uint2 b = split2(f[2 * lq2], f[2 * lq2 + 1]);
                As4[r * A_ST4 + (cb >> 2) + p] = make_uint4(a.x, a.y, b.x, b.y);
            }
        }
        // ---- fill B chunk: copy 16 kqp x 130 uint4 from precomputed image ----
        {
            const uint4* src = (const uint4*)(wimg + (size_t)(c * 16) * 130 * 8);
            for (int i = tid; i < 2080; i += 256) Bs4[i] = src[i];
        }
        __syncthreads();

        // ---- compute: 4 k16-steps, LDS.128 operands ----
#pragma unroll
        for (int t = 0; t < 4; t++) {
            int r = wrow + (lane >> 2);
            int kqp = t * 4 + (lane & 3);
            uint4 A0 = As4[r * A_ST4 + kqp];          // {hi k, lo k, hi k+8, lo k+8} row r
            uint4 A1 = As4[(r + 8) * A_ST4 + kqp];    // row r+8
            int bn = lane >> 2;
#pragma unroll
            for (int nt = 0; nt < 16; nt++) {
                uint4 B = Bs4[kqp * B_ST4 + nt * 8 + bn];
                mma_bf16(d[nt], A0.x, A1.x, A0.z, A1.z, B.x, B.z); // hi*hi
                mma_bf16(d[nt], A0.y, A1.y, A0.w, A1.w, B.x, B.z); // lo*hi
                mma_bf16(d[nt], A0.x, A1.x, A0.z, A1.z, B.y, B.w); // hi*lo
            }
        }
        __syncthreads();
    }

    // ---- epilogue: bias add, store, fused BN stats ----
    float* ssum = (float*)smem;
    float* ssq  = ((float*)smem) + 128;
    ((float*)smem)[tid] = 0.f;
    __syncthreads();

    float* outp = mode ? g_y2 : g_y1;
    int r0 = row0 + wrow + (lane >> 2);
    int r1 = r0 + 8;
    bool v0 = r0 < n, v1 = r1 < n;
#pragma unroll
    for (int nt = 0; nt < 16; nt++) {
        int col = nt * 8 + 2 * (lane & 3);
        float bx = __ldg(&bias[col]);
        float by = __ldg(&bias[col + 1]);
        float e0 = d[nt][0] + bx, e1 = d[nt][1] + by;
        float e2 = d[nt][2] + bx, e3 = d[nt][3] + by;
        if (v0) *(float2*)&outp[(size_t)r0 * HID + col] = make_float2(e0, e1);
        if (v1) *(float2*)&outp[(size_t)r1 * HID + col] = make_float2(e2, e3);
        float u0 = v0 ? e0 : 0.f, u1 = v0 ? e1 : 0.f;
        float u2 = v1 ? e2 : 0.f, u3 = v1 ? e3 : 0.f;
        float s0 = u0 + u2;
        float s1 = u1 + u3;
        float q0 = u0 * u0 + u2 * u2;
        float q1 = u1 * u1 + u3 * u3;
#pragma unroll
        for (int m = 4; m <= 16; m <<= 1) {
            s0 += __shfl_xor_sync(0xffffffffu, s0, m);
            s1 += __shfl_xor_sync(0xffffffffu, s1, m);
            q0 += __shfl_xor_sync(0xffffffffu, q0, m);
            q1 += __shfl_xor_sync(0xffffffffu, q1, m);
        }
        if (lane < 4) {
            atomicAdd(&ssum[col], s0);
            atomicAdd(&ssum[col + 1], s1);
            atomicAdd(&ssq[col], q0);
            atomicAdd(&ssq[col + 1], q1);
        }
    }
    __syncthreads();
    {
        int s = mode;
        if (tid < 128) atomicAdd(&g_sum[s][tid], ssum[tid]);
        else           atomicAdd(&g_sumsq[s][tid - 128], ssq[tid - 128]);
    }
}

// ================= zero accumulators =================
__global__ void zero_kernel(int n) {
    int i = blockIdx.x * blockDim.x + threadIdx.x;
    if (i < n) {
        g_cnt[i] = 0;
        g_fill[i] = 0;
    }
    if (i < 2 * HID) {
        (&g_sum[0][0])[i] = 0.f;
        (&g_sumsq[0][0])[i] = 0.f;
    }
}

// ================= BN finalize / apply =================
__global__ void bn_finalize_kernel(const float* __restrict__ gamma,
                                   const float* __restrict__ beta, int n, int s) {
    int c = threadIdx.x;
    float invN = 1.0f / (float)n;
    float mu  = g_sum[s][c] * invN;
    float var = g_sumsq[s][c] * invN - mu * mu;
    float sc  = rsqrtf(var + EPS) * gamma[c];
    g_scale[s][c] = sc;
    g_shift[s][c] = beta[c] - mu * sc;
}

// which==0: also emit fp16 mirror (feat path, relu=1)
__global__ void bn_apply_kernel(int which, float* __restrict__ out,
                                int n4, int s, int relu) {
    const float* __restrict__ in = which ? g_y2 : g_y1;
    int i = blockIdx.x * blockDim.x + threadIdx.x;
    if (i >= n4) return;
    int c = (i << 2) & (HID - 1);
    float4 v  = ((const float4*)in)[i];
    float4 sc = *(const float4*)&g_scale[s][c];
    float4 sh = *(const float4*)&g_shift[s][c];
    v.x = v.x * sc.x + sh.x;
    v.y = v.y * sc.y + sh.y;
    v.z = v.z * sc.z + sh.z;
    v.w = v.w * sc.w + sh.w;
    if (relu) {
        v.x = fmaxf(v.x, 0.f);
        v.y = fmaxf(v.y, 0.f);
        v.z = fmaxf(v.z, 0.f);
        v.w = fmaxf(v.w, 0.f);
    }
    ((float4*)out)[i] = v;
    if (which == 0) {
        __half2 h0 = __floats2half2_rn(v.x, v.y);
        __half2 h1 = __floats2half2_rn(v.z, v.w);
        uint2 packed;
        packed.x = *(uint32_t*)&h0;
        packed.y = *(uint32_t*)&h1;
        *(uint2*)&g_feat16[(size_t)i * 2] = packed;
    }
}

// ================= CSR build =================
__global__ void count_kernel(const int* __restrict__ ei, int E_) {
    int e = blockIdx.x * blockDim.x + threadIdx.x;
    if (e < E_) atomicAdd(&g_cnt[ei[E_ + e]], 1);
}

__global__ void scan1_kernel(int n) {
    __shared__ int s[1024];
    int i = blockIdx.x * 1024 + threadIdx.x;
    int v = (i < n) ? g_cnt[i] : 0;
    s[threadIdx.x] = v;
    __syncthreads();
#pragma unroll
    for (int off = 1; off < 1024; off <<= 1) {
        int t = (threadIdx.x >= off) ? s[threadIdx.x - off] : 0;
        __syncthreads();
        s[threadIdx.x] += t;
        __syncthreads();
    }
    if (i < n) g_rowstart[i] = s[threadIdx.x] - v;
    if (threadIdx.x == 1023) g_bsum[blockIdx.x] = s[1023];
}

__global__ void scan2_kernel(int nb, int n) {
    if (threadIdx.x == 0) {
        int acc = 0;
        for (int b = 0; b < nb; b++) {
            int t = g_bsum[b];
            g_bsum[b] = acc;
            acc += t;
        }
        g_rowstart[n] = acc;
    }
}

__global__ void scan3_kernel(int n) {
    int i = blockIdx.x * blockDim.x + threadIdx.x;
    if (i < n) g_rowstart[i] += g_bsum[i >> 10];
}

__global__ void fill_kernel(const int* __restrict__ ei, int E_) {
    int e = blockIdx.x * blockDim.x + threadIdx.x;
    if (e >= E_) return;
    int dst = ei[E_ + e];
    int pos = atomicAdd(&g_fill[dst], 1);
    g_srcsorted[g_rowstart[dst] + pos] = ei[e];
}

// ================= aggregate: warp per dst node, fp16 gather =================
__global__ __launch_bounds__(256) void aggregate_kernel(int n) {
    int w = (blockIdx.x * blockDim.x + threadIdx.x) >> 5;
    if (w >= n) return;
    int lane = threadIdx.x & 31;
    int beg = g_rowstart[w];
    int end = g_rowstart[w + 1];

    float4 acc = make_float4(0.f, 0.f, 0.f, 0.f);
    int i = beg;
    for (; i + 4 <= end; i += 4) {
        int s0 = g_srcsorted[i];
        int s1 = g_srcsorted[i + 1];
        int s2 = g_srcsorted[i + 2];
        int s3 = g_srcsorted[i + 3];
        uint2 r0 = *(const uint2*)&g_feat16[(size_t)s0 * 64 + lane * 2];
        uint2 r1 = *(const uint2*)&g_feat16[(size_t)s1 * 64 + lane * 2];
        uint2 r2 = *(const uint2*)&g_feat16[(size_t)s2 * 64 + lane * 2];
        uint2 r3 = *(const uint2*)&g_feat16[(size_t)s3 * 64 + lane * 2];
        float2 a0 = __half22float2(*(__half2*)&r0.x), b0 = __half22float2(*(__half2*)&r0.y);
        float2 a1 = __half22float2(*(__half2*)&r1.x), b1 = __half22float2(*(__half2*)&r1.y);
        float2 a2 = __half22float2(*(__half2*)&r2.x), b2 = __half22float2(*(__half2*)&r2.y);
        float2 a3 = __half22float2(*(__half2*)&r3.x), b3 = __half22float2(*(__half2*)&r3.y);
        acc.x += (a0.x + a1.x) + (a2.x + a3.x);
        acc.y += (a0.y + a1.y) + (a2.y + a3.y);
        acc.z += (b0.x + b1.x) + (b2.x + b3.x);
        acc.w += (b0.y + b1.y) + (b2.y + b3.y);
    }
    for (; i < end; i++) {
        int s0 = g_srcsorted[i];
        uint2 r0 = *(const uint2*)&g_feat16[(size_t)s0 * 64 + lane * 2];
        float2 a0 = __half22float2(*(__half2*)&r0.x), b0 = __half22float2(*(__half2*)&r0.y);
        acc.x += a0.x;
        acc.y += a0.y;
        acc.z += b0.x;
        acc.w += b0.y;
    }
    float inv = 1.0f / fmaxf((float)(end - beg), 1.0f);
    acc.x *= inv;
    acc.y *= inv;
    acc.z *= inv;
    acc.w *= inv;
    *(float4*)&g_msg[w * HID + lane * 4] = acc;
}

// ================= launch =================
extern "C" void kernel_launch(void* const* d_in, const int* in_sizes, int n_in,
                              void* d_out, int out_size) {
    const float* x   = (const float*)d_in[0];
    const int*   ei  = (const int*)d_in[1];
    const float* W1  = (const float*)d_in[2];
    const float* b1  = (const float*)d_in[3];
    const float* g1  = (const float*)d_in[4];
    const float* be1 = (const float*)d_in[5];
    const float* Wl  = (const float*)d_in[6];
    const float* bl  = (const float*)d_in[7];
    const float* Wr  = (const float*)d_in[8];
    const float* g2  = (const float*)d_in[9];
    const float* be2 = (const float*)d_in[10];

    int n  = in_sizes[0] / D_IN;
    int E_ = in_sizes[1] / 2;

    float* feat = (float*)d_out;
    float* out2 = feat + (size_t)n * HID;

    int n4 = n * (HID / 4);
    int eblocks = (E_ + 255) / 256;
    int nblocks = (n + 255) / 256;
    int nb1024 = (n + 1023) / 1024;
    int tblocks = (n + 127) / 128;

    static int smem_set = 0;
    if (!smem_set) {
        cudaFuncSetAttribute(tc_gemm_kernel,
                             cudaFuncAttributeMaxDynamicSharedMemorySize, SM_GTOTAL);
        smem_set = 1;
    }

    // launch order keeps tc_gemm mode0 at index 3 (profiled slot)
    zero_kernel<<<nblocks, 256>>>(n);                                  // 0
    wprep_kernel<<<(2 * 256 * 128 + 255) / 256, 256>>>(W1, Wl, Wr);    // 1
    count_kernel<<<eblocks, 256>>>(ei, E_);                            // 2
    tc_gemm_kernel<<<tblocks, 256, SM_GTOTAL>>>(0, x, b1, n);          // 3 (profiled)
    bn_finalize_kernel<<<1, HID>>>(g1, be1, n, 0);                     // 4
    bn_apply_kernel<<<(n4 + 255) / 256, 256>>>(0, feat, n4, 0, 1);     // 5
    scan1_kernel<<<nb1024, 1024>>>(n);
    scan2_kernel<<<1, 32>>>(nb1024, n);
    scan3_kernel<<<nblocks, 256>>>(n);
    fill_kernel<<<eblocks, 256>>>(ei, E_);
    aggregate_kernel<<<(n * 32 + 255) / 256, 256>>>(n);
    tc_gemm_kernel<<<tblocks, 256, SM_GTOTAL>>>(1, nullptr, bl, n);
    bn_finalize_kernel<<<1, HID>>>(g2, be2, n, 1);
    bn_apply_kernel<<<(n4 + 255) / 256, 256>>>(1, out2, n4, 1, 0);
}